// round 1
// baseline (speedup 1.0000x reference)
#include <cuda_runtime.h>
#include <math.h>

// ESN_67499706024319: x[t] = 0.1*x[t-1] + 0.9*erf(W_res@x[t-1] + u[t]) / sqrt(2048)
// u = input @ W_in^T + bias  (precomputed by proj_kernel into g_proj)
//
// Persistent-kernel design: 128 CTAs, each caches 16 rows of W_res (fp32) in
// SMEM. Per step: matvec from SMEM -> write own 16 outputs to out[t] ->
// fence+flag(release) -> poll all 128 flags(acquire) -> reload out[t] into SMEM.

#define T_SEQ 4096
#define R_DIM 2048
#define K_IN  128
#define NCTA  128
#define NTHR  512
#define ROWS  16               // R_DIM / NCTA
#define NWARP (NTHR / 32)
#define SMEM_BYTES ((ROWS * R_DIM + R_DIM + NWARP * ROWS) * 4)

__device__ float g_proj[(size_t)T_SEQ * R_DIM];
__device__ unsigned int g_flags[NCTA * 32];   // one flag per 128B to avoid line sharing

__global__ void reset_flags() {
    if (threadIdx.x < NCTA) g_flags[threadIdx.x * 32] = 0u;
}

// ---------------- input projection: g_proj[t][r] = sum_k in[t][k]*W_in[r][k] + bias[r]
__global__ void proj_kernel(const float* __restrict__ input,
                            const float* __restrict__ W_in,
                            const float* __restrict__ bias) {
    const int BT = 64, BR = 32;
    __shared__ float sIn[BT * K_IN];
    __shared__ float sW[BR * K_IN];
    const int t0 = blockIdx.x * BT;
    const int r0 = blockIdx.y * BR;
    const int tid = threadIdx.x;

    {
        const float4* a = (const float4*)(input + (size_t)t0 * K_IN);
        float4* d = (float4*)sIn;
        for (int i = tid; i < BT * K_IN / 4; i += 256) d[i] = a[i];
        const float4* b = (const float4*)(W_in + (size_t)r0 * K_IN);
        float4* e = (float4*)sW;
        for (int i = tid; i < BR * K_IN / 4; i += 256) e[i] = b[i];
    }
    __syncthreads();

    const int tl = (tid & 31) * 2;   // 2 t-rows per thread
    const int rl = (tid >> 5) * 4;   // 4 r-cols per thread
    float acc0[4] = {0.f, 0.f, 0.f, 0.f};
    float acc1[4] = {0.f, 0.f, 0.f, 0.f};
    #pragma unroll 4
    for (int k = 0; k < K_IN; k++) {
        float a0 = sIn[tl * K_IN + k];
        float a1 = sIn[(tl + 1) * K_IN + k];
        #pragma unroll
        for (int j = 0; j < 4; j++) {
            float b = sW[(rl + j) * K_IN + k];
            acc0[j] = fmaf(a0, b, acc0[j]);
            acc1[j] = fmaf(a1, b, acc1[j]);
        }
    }
    #pragma unroll
    for (int j = 0; j < 4; j++) {
        float bb = bias[r0 + rl + j];
        g_proj[(size_t)(t0 + tl) * R_DIM + r0 + rl + j] = acc0[j] + bb;
        g_proj[(size_t)(t0 + tl + 1) * R_DIM + r0 + rl + j] = acc1[j] + bb;
    }
}

// ---------------- persistent recurrence kernel
__global__ void __launch_bounds__(NTHR, 1)
esn_kernel(const float* __restrict__ W_res, float* __restrict__ out) {
    extern __shared__ float smem[];
    float* sW   = smem;                    // ROWS * R_DIM  (128 KB)
    float* sX   = sW + ROWS * R_DIM;       // R_DIM         (8 KB)
    float* sRed = sX + R_DIM;              // NWARP * ROWS  (1 KB)

    const int tid  = threadIdx.x;
    const int cta  = blockIdx.x;
    const int row0 = cta * ROWS;
    const int warp = tid >> 5;
    const int lane = tid & 31;

    // Cache this CTA's 16 W_res rows in SMEM (once).
    #pragma unroll
    for (int r = 0; r < ROWS; r++) {
        float4 v = ((const float4*)(W_res + (size_t)(row0 + r) * R_DIM))[tid];
        ((float4*)(sW + r * R_DIM))[tid] = v;
    }
    ((float4*)sX)[tid] = make_float4(0.f, 0.f, 0.f, 0.f);
    __syncthreads();

    const float inv_sqrt = 0.022097086912079610f;  // 1/sqrt(2048)

    for (int t = 0; t < T_SEQ; t++) {
        // Prefetch this step's u and old state early (hidden under compute).
        float u = 0.f, xold = 0.f;
        if (tid < ROWS) {
            u    = g_proj[(size_t)t * R_DIM + row0 + tid];
            xold = sX[row0 + tid];
        }

        // Partial dots: thread owns K-chunk [tid*4, tid*4+4) for all 16 rows.
        float4 xv = ((const float4*)sX)[tid];
        float acc[ROWS];
        #pragma unroll
        for (int r = 0; r < ROWS; r++) {
            float4 w = ((const float4*)(sW + r * R_DIM))[tid];
            acc[r] = fmaf(w.x, xv.x, fmaf(w.y, xv.y, fmaf(w.z, xv.z, w.w * xv.w)));
        }

        // Warp butterfly reduce each row-partial.
        #pragma unroll
        for (int r = 0; r < ROWS; r++) {
            float v = acc[r];
            v += __shfl_xor_sync(0xffffffffu, v, 16);
            v += __shfl_xor_sync(0xffffffffu, v, 8);
            v += __shfl_xor_sync(0xffffffffu, v, 4);
            v += __shfl_xor_sync(0xffffffffu, v, 2);
            v += __shfl_xor_sync(0xffffffffu, v, 1);
            acc[r] = v;
        }
        if (lane == 0) {
            #pragma unroll
            for (int r = 0; r < ROWS; r++) sRed[warp * ROWS + r] = acc[r];
        }
        __syncthreads();

        // Finalize 16 rows, write to out[t].
        if (tid < ROWS) {
            float s = 0.f;
            #pragma unroll
            for (int w = 0; w < NWARP; w++) s += sRed[w * ROWS + tid];
            float pre  = s + u;
            float xnew = 0.1f * xold + 0.9f * erff(pre) * inv_sqrt;
            out[(size_t)t * R_DIM + row0 + tid] = xnew;
            __threadfence();
        }
        __syncthreads();

        // Publish completion of step t.
        if (tid == 0) {
            unsigned int* fl = &g_flags[cta * 32];
            asm volatile("st.release.gpu.global.u32 [%0], %1;"
                         :: "l"(fl), "r"(t + 1) : "memory");
        }
        // Wait for all CTAs (one flag per lane across warps 0-3).
        if (tid < NCTA) {
            const unsigned int* fp = &g_flags[tid * 32];
            unsigned int v;
            do {
                asm volatile("ld.acquire.gpu.global.u32 %0, [%1];"
                             : "=r"(v) : "l"(fp) : "memory");
            } while (v < (unsigned int)(t + 1));
        }
        __syncthreads();

        // Broadcast x_t back into SMEM (out[t] row is L2-resident).
        ((float4*)sX)[tid] = ((const float4*)(out + (size_t)t * R_DIM))[tid];
        __syncthreads();
    }
}

extern "C" void kernel_launch(void* const* d_in, const int* in_sizes, int n_in,
                              void* d_out, int out_size) {
    const float* input = (const float*)d_in[0];   // (4096, 128)
    const float* W_in  = (const float*)d_in[1];   // (2048, 128)
    const float* W_res = (const float*)d_in[2];   // (2048, 2048)
    const float* bias  = (const float*)d_in[3];   // (2048,)
    float* out = (float*)d_out;                   // (4096, 2048)

    cudaFuncSetAttribute(esn_kernel,
                         cudaFuncAttributeMaxDynamicSharedMemorySize, SMEM_BYTES);

    reset_flags<<<1, 128>>>();
    dim3 gproj(T_SEQ / 64, R_DIM / 32);
    proj_kernel<<<gproj, 256>>>(input, W_in, bias);
    esn_kernel<<<NCTA, NTHR, SMEM_BYTES>>>(W_res, out);
}

// round 2
// speedup vs baseline: 1.4115x; 1.4115x over previous
#include <cuda_runtime.h>
#include <math.h>

// ESN: x[t] = 0.1*x[t-1] + 0.9*erf(W_res@x[t-1] + u[t]) / sqrt(2048)
// u = input @ W_in^T + bias  (precomputed into g_proj)
//
// R2 design: persistent kernel, 128 CTAs x 512 threads. Each thread holds its
// 16-row x 4-col block of W_res in REGISTERS (64 floats). Per step:
//   - 64 FFMA from regs  (no SMEM W traffic)
//   - folded butterfly reduce (16 SHFL) -> sRed -> 16 finalizer threads
//   - finalizers: erf, STG out[t], STS own sX chunk, x_old kept in regs
//   - warp0 syncwarp -> lane0 st.release flag
//   - all 512 threads gather: poll flag[src] (acquire), LDG float4, STS sX

#define T_SEQ 4096
#define R_DIM 2048
#define K_IN  128
#define NCTA  128
#define NTHR  512
#define ROWS  16
#define NWARP (NTHR / 32)

__device__ float g_proj[(size_t)T_SEQ * R_DIM];
__device__ unsigned int g_flags[NCTA * 32];   // 128B apart

__global__ void reset_flags() {
    if (threadIdx.x < NCTA) g_flags[threadIdx.x * 32] = 0u;
}

// ---------------- input projection: g_proj[t][r] = sum_k in[t][k]*W_in[r][k] + bias[r]
__global__ void proj_kernel(const float* __restrict__ input,
                            const float* __restrict__ W_in,
                            const float* __restrict__ bias) {
    const int BT = 64, BR = 32;
    __shared__ float sIn[BT * K_IN];
    __shared__ float sW[BR * K_IN];
    const int t0 = blockIdx.x * BT;
    const int r0 = blockIdx.y * BR;
    const int tid = threadIdx.x;

    {
        const float4* a = (const float4*)(input + (size_t)t0 * K_IN);
        float4* d = (float4*)sIn;
        for (int i = tid; i < BT * K_IN / 4; i += 256) d[i] = a[i];
        const float4* b = (const float4*)(W_in + (size_t)r0 * K_IN);
        float4* e = (float4*)sW;
        for (int i = tid; i < BR * K_IN / 4; i += 256) e[i] = b[i];
    }
    __syncthreads();

    const int tl = (tid & 31) * 2;
    const int rl = (tid >> 5) * 4;
    float acc0[4] = {0.f, 0.f, 0.f, 0.f};
    float acc1[4] = {0.f, 0.f, 0.f, 0.f};
    #pragma unroll 4
    for (int k = 0; k < K_IN; k++) {
        float a0 = sIn[tl * K_IN + k];
        float a1 = sIn[(tl + 1) * K_IN + k];
        #pragma unroll
        for (int j = 0; j < 4; j++) {
            float b = sW[(rl + j) * K_IN + k];
            acc0[j] = fmaf(a0, b, acc0[j]);
            acc1[j] = fmaf(a1, b, acc1[j]);
        }
    }
    #pragma unroll
    for (int j = 0; j < 4; j++) {
        float bb = bias[r0 + rl + j];
        g_proj[(size_t)(t0 + tl) * R_DIM + r0 + rl + j] = acc0[j] + bb;
        g_proj[(size_t)(t0 + tl + 1) * R_DIM + r0 + rl + j] = acc1[j] + bb;
    }
}

// ---------------- persistent recurrence kernel
__global__ void __launch_bounds__(NTHR, 1)
esn_kernel(const float* __restrict__ W_res, float* __restrict__ out) {
    __shared__ float sX[R_DIM];            // current state vector (8 KB)
    __shared__ float sRed[NWARP * ROWS];   // cross-warp partials (1 KB)

    const int tid  = threadIdx.x;
    const int cta  = blockIdx.x;
    const int row0 = cta * ROWS;
    const int warp = tid >> 5;
    const int lane = tid & 31;

    // ---- load this thread's W block into registers: rows row0..row0+15,
    //      cols tid*4 .. tid*4+3  (64 regs)
    float4 w[ROWS];
    #pragma unroll
    for (int r = 0; r < ROWS; r++)
        w[r] = ((const float4*)(W_res + (size_t)(row0 + r) * R_DIM))[tid];

    ((float4*)sX)[tid] = make_float4(0.f, 0.f, 0.f, 0.f);

    const float inv_sqrt = 0.022097086912079610f;  // 1/sqrt(2048)
    float u = 0.f, xold = 0.f;
    if (tid < ROWS) u = g_proj[row0 + tid];        // u for t=0

    __syncthreads();

    for (int t = 0; t < T_SEQ; t++) {
        // ---- partial dots from registers
        float4 xv = ((const float4*)sX)[tid];
        float acc[ROWS];
        #pragma unroll
        for (int r = 0; r < ROWS; r++)
            acc[r] = fmaf(w[r].x, xv.x, fmaf(w[r].y, xv.y,
                     fmaf(w[r].z, xv.z, w[r].w * xv.w)));

        // ---- folded butterfly reduce: 16 rows x 32 lanes -> 16 sums
        #pragma unroll
        for (int j = 0; j < 8; j++) {
            float send = (lane & 16) ? acc[j] : acc[j + 8];
            float recv = __shfl_xor_sync(0xffffffffu, send, 16);
            acc[j] = ((lane & 16) ? acc[j + 8] : acc[j]) + recv;
        }
        #pragma unroll
        for (int j = 0; j < 4; j++) {
            float send = (lane & 8) ? acc[j] : acc[j + 4];
            float recv = __shfl_xor_sync(0xffffffffu, send, 8);
            acc[j] = ((lane & 8) ? acc[j + 4] : acc[j]) + recv;
        }
        #pragma unroll
        for (int j = 0; j < 2; j++) {
            float send = (lane & 4) ? acc[j] : acc[j + 2];
            float recv = __shfl_xor_sync(0xffffffffu, send, 4);
            acc[j] = ((lane & 4) ? acc[j + 2] : acc[j]) + recv;
        }
        {
            float send = (lane & 2) ? acc[0] : acc[1];
            float recv = __shfl_xor_sync(0xffffffffu, send, 2);
            acc[0] = ((lane & 2) ? acc[1] : acc[0]) + recv;
        }
        acc[0] += __shfl_xor_sync(0xffffffffu, acc[0], 1);
        // even lane l holds full warp-sum of row (l>>1)
        if (!(lane & 1)) sRed[warp * ROWS + (lane >> 1)] = acc[0];
        __syncthreads();                                   // (A)

        // ---- finalize 16 rows (warp 0)
        if (tid < ROWS) {
            float s = 0.f;
            #pragma unroll
            for (int wi = 0; wi < NWARP; wi++) s += sRed[wi * ROWS + tid];
            float pre  = s + u;
            float xnew = 0.1f * xold + 0.9f * erff(pre) * inv_sqrt;
            xold = xnew;
            out[(size_t)t * R_DIM + row0 + tid] = xnew;
            sX[row0 + tid] = xnew;                         // own chunk locally
            if (t + 1 < T_SEQ) u = g_proj[(size_t)(t + 1) * R_DIM + row0 + tid];
        }
        if (tid < 32) {
            __syncwarp();                                  // order lanes' STGs
            if (tid == 0) {
                unsigned int* fl = &g_flags[cta * 32];
                asm volatile("st.release.gpu.global.u32 [%0], %1;"
                             :: "l"(fl), "r"(t + 1) : "memory");
            }
        }

        // ---- gather other CTAs' chunks: thread tid handles float4 #tid of x
        int src = tid >> 2;                 // source CTA for this float4
        if (src != cta) {
            const unsigned int* fp = &g_flags[src * 32];
            unsigned int v;
            do {
                asm volatile("ld.acquire.gpu.global.u32 %0, [%1];"
                             : "=r"(v) : "l"(fp) : "memory");
            } while (v < (unsigned int)(t + 1));
            float4 xin = ((const float4*)(out + (size_t)t * R_DIM))[tid];
            ((float4*)sX)[tid] = xin;
        }
        __syncthreads();                                   // (C)
    }
}

extern "C" void kernel_launch(void* const* d_in, const int* in_sizes, int n_in,
                              void* d_out, int out_size) {
    const float* input = (const float*)d_in[0];   // (4096, 128)
    const float* W_in  = (const float*)d_in[1];   // (2048, 128)
    const float* W_res = (const float*)d_in[2];   // (2048, 2048)
    const float* bias  = (const float*)d_in[3];   // (2048,)
    float* out = (float*)d_out;                   // (4096, 2048)

    reset_flags<<<1, 128>>>();
    dim3 gproj(T_SEQ / 64, R_DIM / 32);
    proj_kernel<<<gproj, 256>>>(input, W_in, bias);
    esn_kernel<<<NCTA, NTHR>>>(W_res, out);
}